// round 11
// baseline (speedup 1.0000x reference)
#include <cuda_runtime.h>
#include <cuda_fp16.h>
#include <cstdint>

#define Bq 8
#define Tq 2048
#define Dq 1024
#define Hq 64
#define BT (Bq*Tq)
#define NQKV 192

// ---------------- device scratch (static globals: allowed) ----------------
__device__ __half g_wf[NQKV*Dq];          // transposed: [n][k], fp16
__device__ __half g_q [BT*Hq];            // [t][h] fp16
__device__ __half g_k [BT*Hq];            // [t][h] fp16
__device__ __half g_vT[Hq*BT];            // [h][t] fp16
__device__ float  g_po[4][128][128][64];  // 4-way split-K partials
__device__ float2 g_pml[4][128][128];
__device__ int    g_ctr;
__device__ int    g_flag[128];

// ---------------- helpers ----------------
__device__ __forceinline__ void mma_f16(float* c, const uint32_t* a, const uint32_t* b)
{
    asm volatile(
        "mma.sync.aligned.m16n8k16.row.col.f32.f16.f16.f32 "
        "{%0,%1,%2,%3}, {%4,%5,%6,%7}, {%8,%9}, {%0,%1,%2,%3};"
        : "+f"(c[0]), "+f"(c[1]), "+f"(c[2]), "+f"(c[3])
        : "r"(a[0]), "r"(a[1]), "r"(a[2]), "r"(a[3]), "r"(b[0]), "r"(b[1]));
}

__device__ __forceinline__ void ldsm4(uint32_t* r, uint32_t addr)
{
    asm volatile("ldmatrix.sync.aligned.m8n8.x4.shared.b16 {%0,%1,%2,%3}, [%4];"
        : "=r"(r[0]), "=r"(r[1]), "=r"(r[2]), "=r"(r[3]) : "r"(addr));
}

__device__ __forceinline__ float ex2(float x)
{
    float y;
    asm("ex2.approx.f32 %0, %1;" : "=f"(y) : "f"(x));
    return y;
}

__device__ __forceinline__ uint32_t pack_h2(float a, float b)
{
    __half2 t = __floats2half2_rn(a, b);
    return *(uint32_t*)&t;
}

__device__ __forceinline__ uint32_t smem_u32(const void* p) {
    uint32_t a;
    asm("{ .reg .u64 t; cvta.to.shared.u64 t, %1; cvt.u32.u64 %0, t; }"
        : "=r"(a) : "l"(p));
    return a;
}

__device__ __forceinline__ void cp16(uint32_t d, const void* s) {
    asm volatile("cp.async.cg.shared.global [%0], [%1], 16;" :: "r"(d), "l"(s) : "memory");
}
#define CP_COMMIT() asm volatile("cp.async.commit_group;" ::: "memory")
#define CP_WAIT(n)  asm volatile("cp.async.wait_group %0;" :: "n"(n) : "memory")

// ---------------------------------------------------------------------------
// Kernel 0: W -> transposed fp16; resets queue state. grid (32, 3).
// ---------------------------------------------------------------------------
__global__ __launch_bounds__(256) void wsplit_kernel(
    const float* __restrict__ Wq, const float* __restrict__ Wk, const float* __restrict__ Wv)
{
    __shared__ float S[32][65];
    const int kb  = blockIdx.x;        // 32-k block
    const int src = blockIdx.y;
    const int tid = threadIdx.x;

    if (kb == 0 && src == 0) {
        if (tid == 0) g_ctr = 0;
        if (tid < 128) g_flag[tid] = 0;
    }

    const float* W = (src == 0) ? Wq : (src == 1) ? Wk : Wv;

    #pragma unroll
    for (int i = tid; i < 512; i += 256) {
        int kk = i >> 4, h4 = (i & 15) * 4;
        float4 v = *(const float4*)&W[(size_t)(kb*32 + kk)*64 + h4];
        S[kk][h4] = v.x; S[kk][h4+1] = v.y; S[kk][h4+2] = v.z; S[kk][h4+3] = v.w;
    }
    __syncthreads();

    const int n  = tid >> 2;                  // 0..63
    const int kq = (tid & 3) * 8;             // 8 k's per thread
    const size_t go = (size_t)(src*64 + n)*Dq + kb*32 + kq;
    #pragma unroll
    for (int j = 0; j < 8; j += 2) {
        *(__half2*)&g_wf[go + j] = __floats2half2_rn(S[kq + j][n], S[kq + j + 1][n]);
    }
}

// ---------------------------------------------------------------------------
// Kernel 1: fused convert + QKV GEMM, plain fp16, double-buffered, ldmatrix.
// grid = 128 M-tiles, 256 threads, warp tile m64 x n48. (unchanged from R10)
// ---------------------------------------------------------------------------
#define QX  0
#define QW  10240
#define QST 25600
#define QSM_TOTAL (2*QST)

__global__ __launch_bounds__(256) void qkv_gemm_kernel(const float* __restrict__ x)
{
    extern __shared__ char smem[];
    const uint32_t sb = smem_u32(smem);

    const int tid  = threadIdx.x;
    const int lane = tid & 31;
    const int warp = tid >> 5;
    const int m0   = blockIdx.x * 128;
    const int wm   = warp & 1;
    const int wn   = warp >> 1;
    const int rql  = lane >> 2;
    const int qc   = (lane & 3) * 2;

    const int arow = (lane & 7) + (((lane >> 3) & 1) << 3);
    const int acol = (lane >> 4) << 3;
    const uint32_t axoff = (uint32_t)(arow*40 + acol) * 2;
    const int brow = (lane & 7) + ((lane >> 4) << 3);
    const int bcol = ((lane >> 3) & 1) << 3;
    const uint32_t bxoff = (uint32_t)(brow*40 + bcol) * 2;

    float c[4][6][4];
    #pragma unroll
    for (int mt = 0; mt < 4; ++mt)
        #pragma unroll
        for (int nt = 0; nt < 6; ++nt)
            #pragma unroll
            for (int j = 0; j < 4; ++j) c[mt][nt][j] = 0.0f;

    float4 xr[4];

    auto loadX = [&](int kc) {
        #pragma unroll
        for (int j = 0; j < 4; ++j) {
            int i = tid + j*256;
            int r = i >> 3, c4 = i & 7;
            xr[j] = *(const float4*)&x[(size_t)(m0 + r)*Dq + kc + c4*4];
        }
    };
    auto stsX = [&](int stg) {
        char* s = smem + stg*QST;
        #pragma unroll
        for (int j = 0; j < 4; ++j) {
            int i = tid + j*256;
            int r = i >> 3, c4 = i & 7;
            float4 v = xr[j];
            int off = (r*40 + c4*4) * 2;
            *(__half2*)(s + QX + off)     = __floats2half2_rn(v.x, v.y);
            *(__half2*)(s + QX + off + 4) = __floats2half2_rn(v.z, v.w);
        }
    };
    auto cpW = [&](int kc, int stg) {
        uint32_t s = sb + stg*QST;
        #pragma unroll
        for (int i = tid; i < 768; i += 256) {
            int r = i >> 2, c16 = (i & 3) * 8;
            uint32_t off = (uint32_t)(r*40 + c16) * 2;
            cp16(s + QW + off, &g_wf[(size_t)r*Dq + kc + c16]);
        }
    };

    loadX(0);
    cpW(0, 0);
    CP_COMMIT();
    stsX(0);
    CP_WAIT(0);
    __syncthreads();

    for (int i = 0; i < 32; ++i) {
        const int cur = i & 1, nxt = cur ^ 1;
        const int kc = i * 32;
        if (i < 31) {
            cpW(kc + 32, nxt);
            CP_COMMIT();
            loadX(kc + 32);
        }

        const uint32_t sc = sb + cur*QST;

        #pragma unroll
        for (int ks = 0; ks < 2; ++ks) {
            const int k0 = ks*16;
            uint32_t ah[4][4];
            #pragma unroll
            for (int mt = 0; mt < 4; ++mt)
                ldsm4(ah[mt], sc + QX + (uint32_t)((wm*64 + mt*16)*40 + k0)*2 + axoff);
            #pragma unroll
            for (int ntp = 0; ntp < 3; ++ntp) {
                uint32_t wf[4];
                ldsm4(wf, sc + QW + (uint32_t)((wn*48 + ntp*16)*40 + k0)*2 + bxoff);
                #pragma unroll
                for (int mt = 0; mt < 4; ++mt) {
                    mma_f16(c[mt][2*ntp],   ah[mt], &wf[0]);
                    mma_f16(c[mt][2*ntp+1], ah[mt], &wf[2]);
                }
            }
        }

        if (i < 31) stsX(nxt);
        CP_WAIT(0);
        __syncthreads();
    }

    // epilogue: fp32 -> fp16 scatter (q, k row-major; v transposed)
    #pragma unroll
    for (int mt = 0; mt < 4; ++mt) {
        #pragma unroll
        for (int nt = 0; nt < 6; ++nt) {
            const int gc = wn*48 + nt*8 + qc;
            #pragma unroll
            for (int hf = 0; hf < 2; ++hf) {
                const int row = m0 + wm*64 + mt*16 + rql + hf*8;
                float v0 = c[mt][nt][hf*2], v1 = c[mt][nt][hf*2 + 1];
                if (gc < 64) {
                    *(__half2*)&g_q[(size_t)row*Hq + gc] = __floats2half2_rn(v0, v1);
                } else if (gc < 128) {
                    *(__half2*)&g_k[(size_t)row*Hq + gc - 64] = __floats2half2_rn(v0, v1);
                } else {
                    const int h = gc - 128;
                    g_vT[(size_t) h   *BT + row] = __float2half_rn(v0);
                    g_vT[(size_t)(h+1)*BT + row] = __float2half_rn(v1);
                }
            }
        }
    }
}

// ---------------------------------------------------------------------------
// Kernel 2: persistent split-4 flash attention + fused merge, plain fp16.
// grid = 296 (2 CTAs/SM). 512 items: quarter key-ranges per (b,qtile),
// heavy-first. Last of 4 finishers merges.
// ---------------------------------------------------------------------------
#define NITEMS 512
#define AK  0
#define AV  9216
#define ASTG 18432
#define ASM_TOTAL (2*ASTG)
#define SC_LOG2E 0.1803368801111244f   // 0.125 * log2(e)

__global__ __launch_bounds__(256, 2) void attn_kernel(float* __restrict__ out)
{
    extern __shared__ char asmem[];
    __shared__ int s_item, s_done;

    const uint32_t sbA = smem_u32(asmem);
    const int tid   = threadIdx.x;
    const int lane  = tid & 31;
    const int warp  = tid >> 5;
    const int qc    = (lane & 3) * 2;
    const int rql   = lane >> 2;

    const int brow = (lane & 7) + ((lane >> 4) << 3);
    const int bcol = ((lane >> 3) & 1) << 3;
    const uint32_t bnoff = (uint32_t)(brow*72 + bcol) * 2;

    while (true) {
        __syncthreads();
        if (tid == 0) s_item = atomicAdd(&g_ctr, 1);
        __syncthreads();
        const int item = s_item;
        if (item >= NITEMS) break;

        const int qtile  = 15 - (item >> 5);
        const int inner  = item & 31;
        const int b      = inner >> 2;
        const int quarter= inner & 3;
        const int q0     = qtile * 128;
        const int bq     = b*16 + qtile;

        const int len    = 2*qtile + 2;
        const int ktbeg  = (len *  quarter     ) >> 2;
        const int ktend  = (len * (quarter + 1)) >> 2;

        auto issueKV = [&](int kt, int stg) {
            const uint32_t ss = sbA + stg*ASTG;
            const size_t kb = (size_t)(b*Tq + kt*64) * Hq;
            const size_t vb = (size_t)(b*Tq + kt*64);
            #pragma unroll
            for (int i = tid; i < 512; i += 256) {
                int t = i >> 3, h0 = (i & 7) * 8;
                cp16(ss + AK + (uint32_t)(t*72 + h0)*2, &g_k[kb + (size_t)t*Hq + h0]);
            }
            #pragma unroll
            for (int i = tid; i < 512; i += 256) {
                int h = i >> 3, t0 = (i & 7) * 8;
                cp16(ss + AV + (uint32_t)(h*72 + t0)*2, &g_vT[(size_t)h*BT + vb + t0]);
            }
        };

        float o[8][4];
        #pragma unroll
        for (int nt = 0; nt < 8; ++nt)
            #pragma unroll
            for (int j = 0; j < 4; ++j) o[nt][j] = 0.0f;
        float m0r = -1e30f, m1r = -1e30f, l0r = 0.0f, l1r = 0.0f;

        const int row0g = q0 + warp*16 + rql;

        if (ktbeg < ktend) {
            // Q fragments in registers
            uint32_t qf[4][4];
            {
                const size_t rb0 = (size_t)(b*Tq + q0 + warp*16 + rql) * Hq;
                const size_t rb1 = rb0 + 8*Hq;
                #pragma unroll
                for (int ks = 0; ks < 4; ++ks) {
                    int k0 = ks*16 + qc;
                    qf[ks][0] = *(const uint32_t*)&g_q[rb0 + k0];
                    qf[ks][1] = *(const uint32_t*)&g_q[rb1 + k0];
                    qf[ks][2] = *(const uint32_t*)&g_q[rb0 + k0 + 8];
                    qf[ks][3] = *(const uint32_t*)&g_q[rb1 + k0 + 8];
                }
            }

            issueKV(ktbeg, 0);
            CP_COMMIT();
            int stg = 0;

            for (int kt = ktbeg; kt < ktend; ++kt) {
                CP_WAIT(0);
                __syncthreads();
                if (kt + 1 < ktend) { issueKV(kt + 1, stg ^ 1); CP_COMMIT(); }

                const uint32_t ss = sbA + stg*ASTG;

                // ---- S = Q K^T ----
                float s[8][4];
                #pragma unroll
                for (int nt = 0; nt < 8; ++nt)
                    #pragma unroll
                    for (int j = 0; j < 4; ++j) s[nt][j] = 0.0f;

                #pragma unroll
                for (int ks = 0; ks < 4; ++ks) {
                    #pragma unroll
                    for (int ntp = 0; ntp < 4; ++ntp) {
                        uint32_t kf[4];
                        ldsm4(kf, ss + AK + (uint32_t)(ntp*16*72 + ks*16)*2 + bnoff);
                        mma_f16(s[2*ntp],   qf[ks], &kf[0]);
                        mma_f16(s[2*ntp+1], qf[ks], &kf[2]);
                    }
                }

                // ---- scale (exp2 domain) + causal mask ----
                const bool need_mask = (kt >= 2*qtile);
                #pragma unroll
                for (int nt = 0; nt < 8; ++nt) {
                    const int colg = kt*64 + nt*8 + qc;
                    #pragma unroll
                    for (int j = 0; j < 4; ++j) {
                        float v = s[nt][j] * SC_LOG2E;
                        if (need_mask) {
                            int cg = colg + (j & 1);
                            int rg = row0g + ((j >> 1) ? 8 : 0);
                            if (cg > rg) v = -1e30f;
                        }
                        s[nt][j] = v;
                    }
                }

                // ---- warp-local online softmax (base-2) ----
                float mx0 = -1e30f, mx1 = -1e30f;
                #pragma unroll
                for (int nt = 0; nt < 8; ++nt) {
                    mx0 = fmaxf(mx0, fmaxf(s[nt][0], s[nt][1]));
                    mx1 = fmaxf(mx1, fmaxf(s[nt][2], s[nt][3]));
                }
                mx0 = fmaxf(mx0, __shfl_xor_sync(0xffffffffu, mx0, 1));
                mx0 = fmaxf(mx0, __shfl_xor_sync(0xffffffffu, mx0, 2));
                mx1 = fmaxf(mx1, __shfl_xor_sync(0xffffffffu, mx1, 1));
                mx1 = fmaxf(mx1, __shfl_xor_sync(0xffffffffu, mx1, 2));
                const float mn0 = fmaxf(m0r, mx0);
                const float mn1 = fmaxf(m1r, mx1);
                const float al0 = ex2(m0r - mn0);
                const float al1 = ex2(m1r - mn1);
                m0r = mn0; m1r = mn1;

                float sum0 = 0.0f, sum1 = 0.0f;
                uint32_t pha[8], phb[8];
                #pragma unroll
                for (int nt = 0; nt < 8; ++nt) {
                    float p0 = ex2(s[nt][0] - mn0);
                    float p1 = ex2(s[nt][1] - mn0);
                    float p2 = ex2(s[nt][2] - mn1);
                    float p3 = ex2(s[nt][3] - mn1);
                    sum0 += p0 + p1; sum1 += p2 + p3;
                    pha[nt] = pack_h2(p0, p1);
                    phb[nt] = pack_h2(p2, p3);
                }
                sum0 += __shfl_xor_sync(0xffffffffu, sum0, 1);
                sum0 += __shfl_xor_sync(0xffffffffu, sum0, 2);
                sum1 += __shfl_xor_sync(0xffffffffu, sum1, 1);
                sum1 += __shfl_xor_sync(0xffffffffu, sum1, 2);
                l0r = l0r * al0 + sum0;
                l1r = l1r * al1 + sum1;

                #pragma unroll
                for (int nt = 0; nt < 8; ++nt) {
                    o[nt][0] *= al0; o[nt][1] *= al0;
                    o[nt][2] *= al1; o[nt][3] *= al1;
                }

                // ---- O += P V ----
                #pragma unroll
                for (int ks = 0; ks < 4; ++ks) {
                    uint32_t pa[4] = {pha[2*ks], phb[2*ks], pha[2*ks+1], phb[2*ks+1]};
                    #pragma unroll
                    for (int ntp = 0; ntp < 4; ++ntp) {
                        uint32_t vf[4];
                        ldsm4(vf, ss + AV + (uint32_t)(ntp*16*72 + ks*16)*2 + bnoff);
                        mma_f16(o[2*ntp],   pa, &vf[0]);
                        mma_f16(o[2*ntp+1], pa, &vf[2]);
                    }
                }

                stg ^= 1;
            }
        }

        // ---- write unnormalized partials ----
        const int rl0 = warp*16 + rql;
        float* po = &g_po[quarter][bq][0][0];
        #pragma unroll
        for (int nt = 0; nt < 8; ++nt) {
            const int col = nt*8 + qc;
            *(float2*)&po[(size_t)rl0*64 + col]      = make_float2(o[nt][0], o[nt][1]);
            *(float2*)&po[(size_t)(rl0+8)*64 + col]  = make_float2(o[nt][2], o[nt][3]);
        }
        if ((lane & 3) == 0) {
            g_pml[quarter][bq][rl0]     = make_float2(m0r, l0r);
            g_pml[quarter][bq][rl0 + 8] = make_float2(m1r, l1r);
        }

        // ---- last finisher merges (base-2 weights) ----
        __threadfence();
        __syncthreads();
        if (tid == 0) s_done = atomicAdd(&g_flag[bq], 1);
        __syncthreads();
        if (s_done == 3) {
            __threadfence();
            const int r  = tid >> 1;
            const int ch = (tid & 1) * 32;
            float2 P0 = g_pml[0][bq][r];
            float2 P1 = g_pml[1][bq][r];
            float2 P2 = g_pml[2][bq][r];
            float2 P3 = g_pml[3][bq][r];
            float m = fmaxf(fmaxf(P0.x, P1.x), fmaxf(P2.x, P3.x));
            float w0 = ex2(P0.x - m), w1 = ex2(P1.x - m);
            float w2 = ex2(P2.x - m), w3 = ex2(P3.x - m);
            float inv = 1.0f / (w0*P0.y + w1*P1.y + w2*P2.y + w3*P3.y);
            const float4* pa = (const float4*)&g_po[0][bq][r][ch];
            const float4* pb = (const float4*)&g_po[1][bq][r][ch];
            const float4* pc = (const float4*)&g_po[2][bq][r][ch];
            const float4* pd = (const float4*)&g_po[3][bq][r][ch];
            float4* pw = (float4*)&out[((size_t)(b*Tq + q0 + r))*64 + ch];
            #pragma unroll
            for (int j = 0; j < 8; ++j) {
                float4 a = pa[j], c2 = pb[j], d = pc[j], e = pd[j];
                pw[j] = make_float4(
                    (w0*a.x + w1*c2.x + w2*d.x + w3*e.x)*inv,
                    (w0*a.y + w1*c2.y + w2*d.y + w3*e.y)*inv,
                    (w0*a.z + w1*c2.z + w2*d.z + w3*e.z)*inv,
                    (w0*a.w + w1*c2.w + w2*d.w + w3*e.w)*inv);
            }
        }
    }
}

// ---------------------------------------------------------------------------
extern "C" void kernel_launch(void* const* d_in, const int* in_sizes, int n_in,
                              void* d_out, int out_size)
{
    const float* x  = (const float*)d_in[0];
    const float* Wq = (const float*)d_in[1];
    const float* Wk = (const float*)d_in[2];
    const float* Wv = (const float*)d_in[3];
    float* out = (float*)d_out;

    (void)in_sizes; (void)n_in; (void)out_size;

    wsplit_kernel<<<dim3(32, 3), 256>>>(Wq, Wk, Wv);

    cudaFuncSetAttribute(qkv_gemm_kernel,
                         cudaFuncAttributeMaxDynamicSharedMemorySize, QSM_TOTAL);
    qkv_gemm_kernel<<<128, 256, QSM_TOTAL>>>(x);

    cudaFuncSetAttribute(attn_kernel,
                         cudaFuncAttributeMaxDynamicSharedMemorySize, ASM_TOTAL);
    attn_kernel<<<296, 256, ASM_TOTAL>>>(out);
}

// round 12
// speedup vs baseline: 1.1237x; 1.1237x over previous
#include <cuda_runtime.h>
#include <cuda_fp16.h>
#include <cstdint>

#define Bq 8
#define Tq 2048
#define Dq 1024
#define Hq 64
#define BT (Bq*Tq)
#define NQKV 192

// ---------------- device scratch (static globals: allowed) ----------------
__device__ __half g_wf[NQKV*Dq];          // transposed: [n][k], fp16
__device__ __half g_q [BT*Hq];            // [t][h] fp16
__device__ __half g_k [BT*Hq];            // [t][h] fp16
__device__ __half g_vT[Hq*BT];            // [h][t] fp16
__device__ float  g_po[2][128][128][64];  // 2-way split-K partials
__device__ float2 g_pml[2][128][128];
__device__ int    g_ctr;
__device__ int    g_flag[128];

// ---------------- helpers ----------------
__device__ __forceinline__ void mma_f16(float* c, const uint32_t* a, const uint32_t* b)
{
    asm volatile(
        "mma.sync.aligned.m16n8k16.row.col.f32.f16.f16.f32 "
        "{%0,%1,%2,%3}, {%4,%5,%6,%7}, {%8,%9}, {%0,%1,%2,%3};"
        : "+f"(c[0]), "+f"(c[1]), "+f"(c[2]), "+f"(c[3])
        : "r"(a[0]), "r"(a[1]), "r"(a[2]), "r"(a[3]), "r"(b[0]), "r"(b[1]));
}

__device__ __forceinline__ void ldsm4(uint32_t* r, uint32_t addr)
{
    asm volatile("ldmatrix.sync.aligned.m8n8.x4.shared.b16 {%0,%1,%2,%3}, [%4];"
        : "=r"(r[0]), "=r"(r[1]), "=r"(r[2]), "=r"(r[3]) : "r"(addr));
}

__device__ __forceinline__ float ex2(float x)
{
    float y;
    asm("ex2.approx.f32 %0, %1;" : "=f"(y) : "f"(x));
    return y;
}

__device__ __forceinline__ uint32_t pack_h2(float a, float b)
{
    __half2 t = __floats2half2_rn(a, b);
    return *(uint32_t*)&t;
}

__device__ __forceinline__ uint32_t smem_u32(const void* p) {
    uint32_t a;
    asm("{ .reg .u64 t; cvta.to.shared.u64 t, %1; cvt.u32.u64 %0, t; }"
        : "=r"(a) : "l"(p));
    return a;
}

__device__ __forceinline__ void cp16(uint32_t d, const void* s) {
    asm volatile("cp.async.cg.shared.global [%0], [%1], 16;" :: "r"(d), "l"(s) : "memory");
}
#define CP_COMMIT() asm volatile("cp.async.commit_group;" ::: "memory")
#define CP_WAIT(n)  asm volatile("cp.async.wait_group %0;" :: "n"(n) : "memory")

// ---------------------------------------------------------------------------
// Kernel 0: W -> transposed fp16; resets queue state. grid (32, 3).
// ---------------------------------------------------------------------------
__global__ __launch_bounds__(256) void wsplit_kernel(
    const float* __restrict__ Wq, const float* __restrict__ Wk, const float* __restrict__ Wv)
{
    __shared__ float S[32][65];
    const int kb  = blockIdx.x;
    const int src = blockIdx.y;
    const int tid = threadIdx.x;

    if (kb == 0 && src == 0) {
        if (tid == 0) g_ctr = 0;
        if (tid < 128) g_flag[tid] = 0;
    }

    const float* W = (src == 0) ? Wq : (src == 1) ? Wk : Wv;

    #pragma unroll
    for (int i = tid; i < 512; i += 256) {
        int kk = i >> 4, h4 = (i & 15) * 4;
        float4 v = *(const float4*)&W[(size_t)(kb*32 + kk)*64 + h4];
        S[kk][h4] = v.x; S[kk][h4+1] = v.y; S[kk][h4+2] = v.z; S[kk][h4+3] = v.w;
    }
    __syncthreads();

    const int n  = tid >> 2;
    const int kq = (tid & 3) * 8;
    const size_t go = (size_t)(src*64 + n)*Dq + kb*32 + kq;
    #pragma unroll
    for (int j = 0; j < 8; j += 2) {
        *(__half2*)&g_wf[go + j] = __floats2half2_rn(S[kq + j][n], S[kq + j + 1][n]);
    }
}

// ---------------------------------------------------------------------------
// Kernel 1: fused convert + QKV GEMM, plain fp16 (unchanged from R10).
// ---------------------------------------------------------------------------
#define QX  0
#define QW  10240
#define QST 25600
#define QSM_TOTAL (2*QST)

__global__ __launch_bounds__(256) void qkv_gemm_kernel(const float* __restrict__ x)
{
    extern __shared__ char smem[];
    const uint32_t sb = smem_u32(smem);

    const int tid  = threadIdx.x;
    const int lane = tid & 31;
    const int warp = tid >> 5;
    const int m0   = blockIdx.x * 128;
    const int wm   = warp & 1;
    const int wn   = warp >> 1;
    const int rql  = lane >> 2;
    const int qc   = (lane & 3) * 2;

    const int arow = (lane & 7) + (((lane >> 3) & 1) << 3);
    const int acol = (lane >> 4) << 3;
    const uint32_t axoff = (uint32_t)(arow*40 + acol) * 2;
    const int brow = (lane & 7) + ((lane >> 4) << 3);
    const int bcol = ((lane >> 3) & 1) << 3;
    const uint32_t bxoff = (uint32_t)(brow*40 + bcol) * 2;

    float c[4][6][4];
    #pragma unroll
    for (int mt = 0; mt < 4; ++mt)
        #pragma unroll
        for (int nt = 0; nt < 6; ++nt)
            #pragma unroll
            for (int j = 0; j < 4; ++j) c[mt][nt][j] = 0.0f;

    float4 xr[4];

    auto loadX = [&](int kc) {
        #pragma unroll
        for (int j = 0; j < 4; ++j) {
            int i = tid + j*256;
            int r = i >> 3, c4 = i & 7;
            xr[j] = *(const float4*)&x[(size_t)(m0 + r)*Dq + kc + c4*4];
        }
    };
    auto stsX = [&](int stg) {
        char* s = smem + stg*QST;
        #pragma unroll
        for (int j = 0; j < 4; ++j) {
            int i = tid + j*256;
            int r = i >> 3, c4 = i & 7;
            float4 v = xr[j];
            int off = (r*40 + c4*4) * 2;
            *(__half2*)(s + QX + off)     = __floats2half2_rn(v.x, v.y);
            *(__half2*)(s + QX + off + 4) = __floats2half2_rn(v.z, v.w);
        }
    };
    auto cpW = [&](int kc, int stg) {
        uint32_t s = sb + stg*QST;
        #pragma unroll
        for (int i = tid; i < 768; i += 256) {
            int r = i >> 2, c16 = (i & 3) * 8;
            uint32_t off = (uint32_t)(r*40 + c16) * 2;
            cp16(s + QW + off, &g_wf[(size_t)r*Dq + kc + c16]);
        }
    };

    loadX(0);
    cpW(0, 0);
    CP_COMMIT();
    stsX(0);
    CP_WAIT(0);
    __syncthreads();

    for (int i = 0; i < 32; ++i) {
        const int cur = i & 1, nxt = cur ^ 1;
        const int kc = i * 32;
        if (i < 31) {
            cpW(kc + 32, nxt);
            CP_COMMIT();
            loadX(kc + 32);
        }

        const uint32_t sc = sb + cur*QST;

        #pragma unroll
        for (int ks = 0; ks < 2; ++ks) {
            const int k0 = ks*16;
            uint32_t ah[4][4];
            #pragma unroll
            for (int mt = 0; mt < 4; ++mt)
                ldsm4(ah[mt], sc + QX + (uint32_t)((wm*64 + mt*16)*40 + k0)*2 + axoff);
            #pragma unroll
            for (int ntp = 0; ntp < 3; ++ntp) {
                uint32_t wf[4];
                ldsm4(wf, sc + QW + (uint32_t)((wn*48 + ntp*16)*40 + k0)*2 + bxoff);
                #pragma unroll
                for (int mt = 0; mt < 4; ++mt) {
                    mma_f16(c[mt][2*ntp],   ah[mt], &wf[0]);
                    mma_f16(c[mt][2*ntp+1], ah[mt], &wf[2]);
                }
            }
        }

        if (i < 31) stsX(nxt);
        CP_WAIT(0);
        __syncthreads();
    }

    #pragma unroll
    for (int mt = 0; mt < 4; ++mt) {
        #pragma unroll
        for (int nt = 0; nt < 6; ++nt) {
            const int gc = wn*48 + nt*8 + qc;
            #pragma unroll
            for (int hf = 0; hf < 2; ++hf) {
                const int row = m0 + wm*64 + mt*16 + rql + hf*8;
                float v0 = c[mt][nt][hf*2], v1 = c[mt][nt][hf*2 + 1];
                if (gc < 64) {
                    *(__half2*)&g_q[(size_t)row*Hq + gc] = __floats2half2_rn(v0, v1);
                } else if (gc < 128) {
                    *(__half2*)&g_k[(size_t)row*Hq + gc - 64] = __floats2half2_rn(v0, v1);
                } else {
                    const int h = gc - 128;
                    g_vT[(size_t) h   *BT + row] = __float2half_rn(v0);
                    g_vT[(size_t)(h+1)*BT + row] = __float2half_rn(v1);
                }
            }
        }
    }
}

// ---------------------------------------------------------------------------
// Kernel 2: persistent split-2 flash attention + fused merge, plain fp16,
// BN=128 key tiles (halves per-iteration fixed overhead). grid = 148.
// ---------------------------------------------------------------------------
#define NITEMS 256
#define AK  0
#define AV  18432                      // K: 128*72*2 = 18432
#define ASTG 35840                     // + V: 64*136*2 = 17408
#define ASM_TOTAL (2*ASTG)
#define SC_LOG2E 0.1803368801111244f   // 0.125 * log2(e)

__global__ __launch_bounds__(256, 1) void attn_kernel(float* __restrict__ out)
{
    extern __shared__ char asmem[];
    __shared__ int s_item, s_done;

    const uint32_t sbA = smem_u32(asmem);
    const int tid   = threadIdx.x;
    const int lane  = tid & 31;
    const int warp  = tid >> 5;
    const int qc    = (lane & 3) * 2;
    const int rql   = lane >> 2;

    const int brow = (lane & 7) + ((lane >> 4) << 3);
    const int bcol = ((lane >> 3) & 1) << 3;
    const uint32_t bkoff = (uint32_t)(brow*72  + bcol) * 2;   // K tiles, stride 72
    const uint32_t bvoff = (uint32_t)(brow*136 + bcol) * 2;   // V tiles, stride 136

    while (true) {
        __syncthreads();
        if (tid == 0) s_item = atomicAdd(&g_ctr, 1);
        __syncthreads();
        const int item = s_item;
        if (item >= NITEMS) break;

        const int qtile = 15 - (item >> 4);
        const int inner = item & 15;
        const int b     = inner >> 1;
        const int half  = inner & 1;
        const int q0    = qtile * 128;
        const int bq    = b*16 + qtile;

        const int len   = qtile + 1;                 // 128-wide key tiles
        const int ktbeg = (len *  half     ) >> 1;
        const int ktend = (len * (half + 1)) >> 1;

        auto issueKV = [&](int kt, int stg) {
            const uint32_t ss = sbA + stg*ASTG;
            const size_t kb = (size_t)(b*Tq + kt*128) * Hq;
            const size_t vb = (size_t)(b*Tq + kt*128);
            #pragma unroll
            for (int i = tid; i < 1024; i += 256) {
                int t = i >> 3, h0 = (i & 7) * 8;
                cp16(ss + AK + (uint32_t)(t*72 + h0)*2, &g_k[kb + (size_t)t*Hq + h0]);
            }
            #pragma unroll
            for (int i = tid; i < 1024; i += 256) {
                int h = i >> 4, t0 = (i & 15) * 8;
                cp16(ss + AV + (uint32_t)(h*136 + t0)*2, &g_vT[(size_t)h*BT + vb + t0]);
            }
        };

        float o[8][4];
        #pragma unroll
        for (int nt = 0; nt < 8; ++nt)
            #pragma unroll
            for (int j = 0; j < 4; ++j) o[nt][j] = 0.0f;
        float m0r = -1e30f, m1r = -1e30f, l0r = 0.0f, l1r = 0.0f;

        const int row0g = q0 + warp*16 + rql;

        if (ktbeg < ktend) {
            // Q fragments in registers
            uint32_t qf[4][4];
            {
                const size_t rb0 = (size_t)(b*Tq + q0 + warp*16 + rql) * Hq;
                const size_t rb1 = rb0 + 8*Hq;
                #pragma unroll
                for (int ks = 0; ks < 4; ++ks) {
                    int k0 = ks*16 + qc;
                    qf[ks][0] = *(const uint32_t*)&g_q[rb0 + k0];
                    qf[ks][1] = *(const uint32_t*)&g_q[rb1 + k0];
                    qf[ks][2] = *(const uint32_t*)&g_q[rb0 + k0 + 8];
                    qf[ks][3] = *(const uint32_t*)&g_q[rb1 + k0 + 8];
                }
            }

            issueKV(ktbeg, 0);
            CP_COMMIT();
            int stg = 0;

            for (int kt = ktbeg; kt < ktend; ++kt) {
                CP_WAIT(0);
                __syncthreads();
                if (kt + 1 < ktend) { issueKV(kt + 1, stg ^ 1); CP_COMMIT(); }

                const uint32_t ss = sbA + stg*ASTG;

                // ---- S = Q K^T  (16 n-tiles of 8) ----
                float s[16][4];
                #pragma unroll
                for (int nt = 0; nt < 16; ++nt)
                    #pragma unroll
                    for (int j = 0; j < 4; ++j) s[nt][j] = 0.0f;

                #pragma unroll
                for (int ks = 0; ks < 4; ++ks) {
                    #pragma unroll
                    for (int ntp = 0; ntp < 8; ++ntp) {
                        uint32_t kf[4];
                        ldsm4(kf, ss + AK + (uint32_t)(ntp*16*72 + ks*16)*2 + bkoff);
                        mma_f16(s[2*ntp],   qf[ks], &kf[0]);
                        mma_f16(s[2*ntp+1], qf[ks], &kf[2]);
                    }
                }

                // ---- scale (exp2 domain) + causal mask ----
                const bool need_mask = (kt == qtile);
                #pragma unroll
                for (int nt = 0; nt < 16; ++nt) {
                    const int colg = kt*128 + nt*8 + qc;
                    #pragma unroll
                    for (int j = 0; j < 4; ++j) {
                        float v = s[nt][j] * SC_LOG2E;
                        if (need_mask) {
                            int cg = colg + (j & 1);
                            int rg = row0g + ((j >> 1) ? 8 : 0);
                            if (cg > rg) v = -1e30f;
                        }
                        s[nt][j] = v;
                    }
                }

                // ---- warp-local online softmax (base-2) ----
                float mx0 = -1e30f, mx1 = -1e30f;
                #pragma unroll
                for (int nt = 0; nt < 16; ++nt) {
                    mx0 = fmaxf(mx0, fmaxf(s[nt][0], s[nt][1]));
                    mx1 = fmaxf(mx1, fmaxf(s[nt][2], s[nt][3]));
                }
                mx0 = fmaxf(mx0, __shfl_xor_sync(0xffffffffu, mx0, 1));
                mx0 = fmaxf(mx0, __shfl_xor_sync(0xffffffffu, mx0, 2));
                mx1 = fmaxf(mx1, __shfl_xor_sync(0xffffffffu, mx1, 1));
                mx1 = fmaxf(mx1, __shfl_xor_sync(0xffffffffu, mx1, 2));
                const float mn0 = fmaxf(m0r, mx0);
                const float mn1 = fmaxf(m1r, mx1);
                const float al0 = ex2(m0r - mn0);
                const float al1 = ex2(m1r - mn1);
                m0r = mn0; m1r = mn1;

                float sum0 = 0.0f, sum1 = 0.0f;
                uint32_t pha[16], phb[16];
                #pragma unroll
                for (int nt = 0; nt < 16; ++nt) {
                    float p0 = ex2(s[nt][0] - mn0);
                    float p1 = ex2(s[nt][1] - mn0);
                    float p2 = ex2(s[nt][2] - mn1);
                    float p3 = ex2(s[nt][3] - mn1);
                    sum0 += p0 + p1; sum1 += p2 + p3;
                    pha[nt] = pack_h2(p0, p1);
                    phb[nt] = pack_h2(p2, p3);
                }
                sum0 += __shfl_xor_sync(0xffffffffu, sum0, 1);
                sum0 += __shfl_xor_sync(0xffffffffu, sum0, 2);
                sum1 += __shfl_xor_sync(0xffffffffu, sum1, 1);
                sum1 += __shfl_xor_sync(0xffffffffu, sum1, 2);
                l0r = l0r * al0 + sum0;
                l1r = l1r * al1 + sum1;

                #pragma unroll
                for (int nt = 0; nt < 8; ++nt) {
                    o[nt][0] *= al0; o[nt][1] *= al0;
                    o[nt][2] *= al1; o[nt][3] *= al1;
                }

                // ---- O += P V  (k-dim = 128 keys -> 8 ks steps) ----
                #pragma unroll
                for (int ks = 0; ks < 8; ++ks) {
                    uint32_t pa[4] = {pha[2*ks], phb[2*ks], pha[2*ks+1], phb[2*ks+1]};
                    #pragma unroll
                    for (int ntp = 0; ntp < 4; ++ntp) {
                        uint32_t vf[4];
                        ldsm4(vf, ss + AV + (uint32_t)(ntp*16*136 + ks*16)*2 + bvoff);
                        mma_f16(o[2*ntp],   pa, &vf[0]);
                        mma_f16(o[2*ntp+1], pa, &vf[2]);
                    }
                }

                stg ^= 1;
            }
        }

        // ---- write unnormalized partials ----
        const int rl0 = warp*16 + rql;
        float* po = &g_po[half][bq][0][0];
        #pragma unroll
        for (int nt = 0; nt < 8; ++nt) {
            const int col = nt*8 + qc;
            *(float2*)&po[(size_t)rl0*64 + col]      = make_float2(o[nt][0], o[nt][1]);
            *(float2*)&po[(size_t)(rl0+8)*64 + col]  = make_float2(o[nt][2], o[nt][3]);
        }
        if ((lane & 3) == 0) {
            g_pml[half][bq][rl0]     = make_float2(m0r, l0r);
            g_pml[half][bq][rl0 + 8] = make_float2(m1r, l1r);
        }

        // ---- last finisher merges (base-2 weights) ----
        __threadfence();
        __syncthreads();
        if (tid == 0) s_done = atomicAdd(&g_flag[bq], 1);
        __syncthreads();
        if (s_done == 1) {
            __threadfence();
            const int r  = tid >> 1;
            const int ch = (tid & 1) * 32;
            float2 A  = g_pml[0][bq][r];
            float2 Bv = g_pml[1][bq][r];
            float m  = fmaxf(A.x, Bv.x);
            float wA = ex2(A.x - m);
            float wB = ex2(Bv.x - m);
            float inv = 1.0f / (wA*A.y + wB*Bv.y);
            const float4* pa = (const float4*)&g_po[0][bq][r][ch];
            const float4* pb = (const float4*)&g_po[1][bq][r][ch];
            float4* pw = (float4*)&out[((size_t)(b*Tq + q0 + r))*64 + ch];
            #pragma unroll
            for (int j = 0; j < 8; ++j) {
                float4 a = pa[j], c = pb[j];
                pw[j] = make_float4((wA*a.x + wB*c.x)*inv, (wA*a.y + wB*c.y)*inv,
                                    (wA*a.z + wB*c.z)*inv, (wA*a.w + wB*c.w)*inv);
            }
        }
    }
}

// ---------------------------------------------------------------------------
extern "C" void kernel_launch(void* const* d_in, const int* in_sizes, int n_in,
                              void* d_out, int out_size)
{
    const float* x  = (const float*)d_in[0];
    const float* Wq = (const float*)d_in[1];
    const float* Wk = (const float*)d_in[2];
    const float* Wv = (const float*)d_in[3];
    float* out = (float*)d_out;

    (void)in_sizes; (void)n_in; (void)out_size;

    wsplit_kernel<<<dim3(32, 3), 256>>>(Wq, Wk, Wv);

    cudaFuncSetAttribute(qkv_gemm_kernel,
                         cudaFuncAttributeMaxDynamicSharedMemorySize, QSM_TOTAL);
    qkv_gemm_kernel<<<128, 256, QSM_TOTAL>>>(x);

    cudaFuncSetAttribute(attn_kernel,
                         cudaFuncAttributeMaxDynamicSharedMemorySize, ASM_TOTAL);
    attn_kernel<<<148, 256, ASM_TOTAL>>>(out);
}

// round 13
// speedup vs baseline: 1.1596x; 1.0319x over previous
#include <cuda_runtime.h>
#include <cuda_fp16.h>
#include <cstdint>

#define Bq 8
#define Tq 2048
#define Dq 1024
#define Hq 64
#define BT (Bq*Tq)
#define NQKV 192

// ---------------- device scratch (static globals: allowed) ----------------
__device__ __half g_wf[NQKV*Dq];          // transposed: [n][k], fp16
__device__ __half g_q [BT*Hq];            // [t][h] fp16
__device__ __half g_k [BT*Hq];            // [t][h] fp16
__device__ __half g_vT[Hq*BT];            // [h][t] fp16
__device__ float  g_po[2][128][128][64];  // 2-way split-K partials
__device__ float2 g_pml[2][128][128];
__device__ int    g_ctr;
__device__ int    g_flag[128];

// ---------------- helpers ----------------
__device__ __forceinline__ void mma_f16(float* c, const uint32_t* a, const uint32_t* b)
{
    asm volatile(
        "mma.sync.aligned.m16n8k16.row.col.f32.f16.f16.f32 "
        "{%0,%1,%2,%3}, {%4,%5,%6,%7}, {%8,%9}, {%0,%1,%2,%3};"
        : "+f"(c[0]), "+f"(c[1]), "+f"(c[2]), "+f"(c[3])
        : "r"(a[0]), "r"(a[1]), "r"(a[2]), "r"(a[3]), "r"(b[0]), "r"(b[1]));
}

__device__ __forceinline__ void ldsm4(uint32_t* r, uint32_t addr)
{
    asm volatile("ldmatrix.sync.aligned.m8n8.x4.shared.b16 {%0,%1,%2,%3}, [%4];"
        : "=r"(r[0]), "=r"(r[1]), "=r"(r[2]), "=r"(r[3]) : "r"(addr));
}

__device__ __forceinline__ float ex2(float x)
{
    float y;
    asm("ex2.approx.f32 %0, %1;" : "=f"(y) : "f"(x));
    return y;
}

__device__ __forceinline__ uint32_t ex2_h2(uint32_t x)
{
    uint32_t y;
    asm("ex2.approx.f16x2 %0, %1;" : "=r"(y) : "r"(x));
    return y;
}

__device__ __forceinline__ uint32_t hsub2(uint32_t a, uint32_t b)
{
    uint32_t d;
    asm("sub.f16x2 %0, %1, %2;" : "=r"(d) : "r"(a), "r"(b));
    return d;
}

__device__ __forceinline__ uint32_t pack_h2(float a, float b)
{
    __half2 t = __floats2half2_rn(a, b);
    return *(uint32_t*)&t;
}

__device__ __forceinline__ uint32_t smem_u32(const void* p) {
    uint32_t a;
    asm("{ .reg .u64 t; cvta.to.shared.u64 t, %1; cvt.u32.u64 %0, t; }"
        : "=r"(a) : "l"(p));
    return a;
}

__device__ __forceinline__ void cp16(uint32_t d, const void* s) {
    asm volatile("cp.async.cg.shared.global [%0], [%1], 16;" :: "r"(d), "l"(s) : "memory");
}
#define CP_COMMIT() asm volatile("cp.async.commit_group;" ::: "memory")
#define CP_WAIT(n)  asm volatile("cp.async.wait_group %0;" :: "n"(n) : "memory")

// ---------------------------------------------------------------------------
// Kernel 0: W -> transposed fp16; resets queue state. grid (32, 3).
// ---------------------------------------------------------------------------
__global__ __launch_bounds__(256) void wsplit_kernel(
    const float* __restrict__ Wq, const float* __restrict__ Wk, const float* __restrict__ Wv)
{
    __shared__ float S[32][65];
    const int kb  = blockIdx.x;
    const int src = blockIdx.y;
    const int tid = threadIdx.x;

    if (kb == 0 && src == 0) {
        if (tid == 0) g_ctr = 0;
        if (tid < 128) g_flag[tid] = 0;
    }

    const float* W = (src == 0) ? Wq : (src == 1) ? Wk : Wv;

    #pragma unroll
    for (int i = tid; i < 512; i += 256) {
        int kk = i >> 4, h4 = (i & 15) * 4;
        float4 v = *(const float4*)&W[(size_t)(kb*32 + kk)*64 + h4];
        S[kk][h4] = v.x; S[kk][h4+1] = v.y; S[kk][h4+2] = v.z; S[kk][h4+3] = v.w;
    }
    __syncthreads();

    const int n  = tid >> 2;
    const int kq = (tid & 3) * 8;
    const size_t go = (size_t)(src*64 + n)*Dq + kb*32 + kq;
    #pragma unroll
    for (int j = 0; j < 8; j += 2) {
        *(__half2*)&g_wf[go + j] = __floats2half2_rn(S[kq + j][n], S[kq + j + 1][n]);
    }
}

// ---------------------------------------------------------------------------
// Kernel 1: fused convert + QKV GEMM, plain fp16 (unchanged from R12).
// ---------------------------------------------------------------------------
#define QX  0
#define QW  10240
#define QST 25600
#define QSM_TOTAL (2*QST)

__global__ __launch_bounds__(256) void qkv_gemm_kernel(const float* __restrict__ x)
{
    extern __shared__ char smem[];
    const uint32_t sb = smem_u32(smem);

    const int tid  = threadIdx.x;
    const int lane = tid & 31;
    const int warp = tid >> 5;
    const int m0   = blockIdx.x * 128;
    const int wm   = warp & 1;
    const int wn   = warp >> 1;
    const int rql  = lane >> 2;
    const int qc   = (lane & 3) * 2;

    const int arow = (lane & 7) + (((lane >> 3) & 1) << 3);
    const int acol = (lane >> 4) << 3;
    const uint32_t axoff = (uint32_t)(arow*40 + acol) * 2;
    const int brow = (lane & 7) + ((lane >> 4) << 3);
    const int bcol = ((lane >> 3) & 1) << 3;
    const uint32_t bxoff = (uint32_t)(brow*40 + bcol) * 2;

    float c[4][6][4];
    #pragma unroll
    for (int mt = 0; mt < 4; ++mt)
        #pragma unroll
        for (int nt = 0; nt < 6; ++nt)
            #pragma unroll
            for (int j = 0; j < 4; ++j) c[mt][nt][j] = 0.0f;

    float4 xr[4];

    auto loadX = [&](int kc) {
        #pragma unroll
        for (int j = 0; j < 4; ++j) {
            int i = tid + j*256;
            int r = i >> 3, c4 = i & 7;
            xr[j] = *(const float4*)&x[(size_t)(m0 + r)*Dq + kc + c4*4];
        }
    };
    auto stsX = [&](int stg) {
        char* s = smem + stg*QST;
        #pragma unroll
        for (int j = 0; j < 4; ++j) {
            int i = tid + j*256;
            int r = i >> 3, c4 = i & 7;
            float4 v = xr[j];
            int off = (r*40 + c4*4) * 2;
            *(__half2*)(s + QX + off)     = __floats2half2_rn(v.x, v.y);
            *(__half2*)(s + QX + off + 4) = __floats2half2_rn(v.z, v.w);
        }
    };
    auto cpW = [&](int kc, int stg) {
        uint32_t s = sb + stg*QST;
        #pragma unroll
        for (int i = tid; i < 768; i += 256) {
            int r = i >> 2, c16 = (i & 3) * 8;
            uint32_t off = (uint32_t)(r*40 + c16) * 2;
            cp16(s + QW + off, &g_wf[(size_t)r*Dq + kc + c16]);
        }
    };

    loadX(0);
    cpW(0, 0);
    CP_COMMIT();
    stsX(0);
    CP_WAIT(0);
    __syncthreads();

    for (int i = 0; i < 32; ++i) {
        const int cur = i & 1, nxt = cur ^ 1;
        const int kc = i * 32;
        if (i < 31) {
            cpW(kc + 32, nxt);
            CP_COMMIT();
            loadX(kc + 32);
        }

        const uint32_t sc = sb + cur*QST;

        #pragma unroll
        for (int ks = 0; ks < 2; ++ks) {
            const int k0 = ks*16;
            uint32_t ah[4][4];
            #pragma unroll
            for (int mt = 0; mt < 4; ++mt)
                ldsm4(ah[mt], sc + QX + (uint32_t)((wm*64 + mt*16)*40 + k0)*2 + axoff);
            #pragma unroll
            for (int ntp = 0; ntp < 3; ++ntp) {
                uint32_t wf[4];
                ldsm4(wf, sc + QW + (uint32_t)((wn*48 + ntp*16)*40 + k0)*2 + bxoff);
                #pragma unroll
                for (int mt = 0; mt < 4; ++mt) {
                    mma_f16(c[mt][2*ntp],   ah[mt], &wf[0]);
                    mma_f16(c[mt][2*ntp+1], ah[mt], &wf[2]);
                }
            }
        }

        if (i < 31) stsX(nxt);
        CP_WAIT(0);
        __syncthreads();
    }

    #pragma unroll
    for (int mt = 0; mt < 4; ++mt) {
        #pragma unroll
        for (int nt = 0; nt < 6; ++nt) {
            const int gc = wn*48 + nt*8 + qc;
            #pragma unroll
            for (int hf = 0; hf < 2; ++hf) {
                const int row = m0 + wm*64 + mt*16 + rql + hf*8;
                float v0 = c[mt][nt][hf*2], v1 = c[mt][nt][hf*2 + 1];
                if (gc < 64) {
                    *(__half2*)&g_q[(size_t)row*Hq + gc] = __floats2half2_rn(v0, v1);
                } else if (gc < 128) {
                    *(__half2*)&g_k[(size_t)row*Hq + gc - 64] = __floats2half2_rn(v0, v1);
                } else {
                    const int h = gc - 128;
                    g_vT[(size_t) h   *BT + row] = __float2half_rn(v0);
                    g_vT[(size_t)(h+1)*BT + row] = __float2half_rn(v1);
                }
            }
        }
    }
}

// ---------------------------------------------------------------------------
// Kernel 2: persistent split-2 flash attention + fused merge, BN=128,
// fp16 ex2 softmax, row-sum l via ones-column MMA. grid = 148.
// ---------------------------------------------------------------------------
#define NITEMS 256
#define AK  0
#define AV  18432                      // K: 128*72*2 = 18432
#define ASTG 35840                     // + V: 64*136*2 = 17408
#define ASM_TOTAL (2*ASTG)
#define SC_LOG2E 0.1803368801111244f   // 0.125 * log2(e)

__global__ __launch_bounds__(256, 1) void attn_kernel(float* __restrict__ out)
{
    extern __shared__ char asmem[];
    __shared__ int s_item, s_done;

    const uint32_t sbA = smem_u32(asmem);
    const int tid   = threadIdx.x;
    const int lane  = tid & 31;
    const int warp  = tid >> 5;
    const int qc    = (lane & 3) * 2;
    const int rql   = lane >> 2;

    const int brow = (lane & 7) + ((lane >> 4) << 3);
    const int bcol = ((lane >> 3) & 1) << 3;
    const uint32_t bkoff = (uint32_t)(brow*72  + bcol) * 2;   // K tiles, stride 72
    const uint32_t bvoff = (uint32_t)(brow*136 + bcol) * 2;   // V tiles, stride 136

    const uint32_t ones_b[2] = {0x3C003C00u, 0x3C003C00u};    // fp16 1.0 x4

    while (true) {
        __syncthreads();
        if (tid == 0) s_item = atomicAdd(&g_ctr, 1);
        __syncthreads();
        const int item = s_item;
        if (item >= NITEMS) break;

        const int qtile = 15 - (item >> 4);
        const int inner = item & 15;
        const int b     = inner >> 1;
        const int half  = inner & 1;
        const int q0    = qtile * 128;
        const int bq    = b*16 + qtile;

        const int len   = qtile + 1;
        const int ktbeg = (len *  half     ) >> 1;
        const int ktend = (len * (half + 1)) >> 1;

        auto issueKV = [&](int kt, int stg) {
            const uint32_t ss = sbA + stg*ASTG;
            const size_t kb = (size_t)(b*Tq + kt*128) * Hq;
            const size_t vb = (size_t)(b*Tq + kt*128);
            #pragma unroll
            for (int i = tid; i < 1024; i += 256) {
                int t = i >> 3, h0 = (i & 7) * 8;
                cp16(ss + AK + (uint32_t)(t*72 + h0)*2, &g_k[kb + (size_t)t*Hq + h0]);
            }
            #pragma unroll
            for (int i = tid; i < 1024; i += 256) {
                int h = i >> 4, t0 = (i & 15) * 8;
                cp16(ss + AV + (uint32_t)(h*136 + t0)*2, &g_vT[(size_t)h*BT + vb + t0]);
            }
        };

        float o[8][4];
        #pragma unroll
        for (int nt = 0; nt < 8; ++nt)
            #pragma unroll
            for (int j = 0; j < 4; ++j) o[nt][j] = 0.0f;
        float lacc[4] = {0.0f, 0.0f, 0.0f, 0.0f};
        float m0r = -1e30f, m1r = -1e30f;

        const int row0g = q0 + warp*16 + rql;

        if (ktbeg < ktend) {
            uint32_t qf[4][4];
            {
                const size_t rb0 = (size_t)(b*Tq + q0 + warp*16 + rql) * Hq;
                const size_t rb1 = rb0 + 8*Hq;
                #pragma unroll
                for (int ks = 0; ks < 4; ++ks) {
                    int k0 = ks*16 + qc;
                    qf[ks][0] = *(const uint32_t*)&g_q[rb0 + k0];
                    qf[ks][1] = *(const uint32_t*)&g_q[rb1 + k0];
                    qf[ks][2] = *(const uint32_t*)&g_q[rb0 + k0 + 8];
                    qf[ks][3] = *(const uint32_t*)&g_q[rb1 + k0 + 8];
                }
            }

            issueKV(ktbeg, 0);
            CP_COMMIT();
            int stg = 0;

            for (int kt = ktbeg; kt < ktend; ++kt) {
                CP_WAIT(0);
                __syncthreads();
                if (kt + 1 < ktend) { issueKV(kt + 1, stg ^ 1); CP_COMMIT(); }

                const uint32_t ss = sbA + stg*ASTG;

                // ---- S = Q K^T ----
                float s[16][4];
                #pragma unroll
                for (int nt = 0; nt < 16; ++nt)
                    #pragma unroll
                    for (int j = 0; j < 4; ++j) s[nt][j] = 0.0f;

                #pragma unroll
                for (int ks = 0; ks < 4; ++ks) {
                    #pragma unroll
                    for (int ntp = 0; ntp < 8; ++ntp) {
                        uint32_t kf[4];
                        ldsm4(kf, ss + AK + (uint32_t)(ntp*16*72 + ks*16)*2 + bkoff);
                        mma_f16(s[2*ntp],   qf[ks], &kf[0]);
                        mma_f16(s[2*ntp+1], qf[ks], &kf[2]);
                    }
                }

                // ---- scale (exp2 domain) + causal mask ----
                const bool need_mask = (kt == qtile);
                #pragma unroll
                for (int nt = 0; nt < 16; ++nt) {
                    const int colg = kt*128 + nt*8 + qc;
                    #pragma unroll
                    for (int j = 0; j < 4; ++j) {
                        float v = s[nt][j] * SC_LOG2E;
                        if (need_mask) {
                            int cg = colg + (j & 1);
                            int rg = row0g + ((j >> 1) ? 8 : 0);
                            if (cg > rg) v = -1e30f;
                        }
                        s[nt][j] = v;
                    }
                }

                // ---- warp-local online softmax (base-2, fp16 ex2) ----
                float mx0 = -1e30f, mx1 = -1e30f;
                #pragma unroll
                for (int nt = 0; nt < 16; ++nt) {
                    mx0 = fmaxf(mx0, fmaxf(s[nt][0], s[nt][1]));
                    mx1 = fmaxf(mx1, fmaxf(s[nt][2], s[nt][3]));
                }
                mx0 = fmaxf(mx0, __shfl_xor_sync(0xffffffffu, mx0, 1));
                mx0 = fmaxf(mx0, __shfl_xor_sync(0xffffffffu, mx0, 2));
                mx1 = fmaxf(mx1, __shfl_xor_sync(0xffffffffu, mx1, 1));
                mx1 = fmaxf(mx1, __shfl_xor_sync(0xffffffffu, mx1, 2));
                const float mn0 = fmaxf(m0r, mx0);
                const float mn1 = fmaxf(m1r, mx1);
                const float al0 = ex2(m0r - mn0);
                const float al1 = ex2(m1r - mn1);
                m0r = mn0; m1r = mn1;

                const uint32_t mn0h = pack_h2(mn0, mn0);
                const uint32_t mn1h = pack_h2(mn1, mn1);
                uint32_t pha[16], phb[16];
                #pragma unroll
                for (int nt = 0; nt < 16; ++nt) {
                    pha[nt] = ex2_h2(hsub2(pack_h2(s[nt][0], s[nt][1]), mn0h));
                    phb[nt] = ex2_h2(hsub2(pack_h2(s[nt][2], s[nt][3]), mn1h));
                }

                lacc[0] *= al0; lacc[1] *= al0;
                lacc[2] *= al1; lacc[3] *= al1;
                #pragma unroll
                for (int nt = 0; nt < 8; ++nt) {
                    o[nt][0] *= al0; o[nt][1] *= al0;
                    o[nt][2] *= al1; o[nt][3] *= al1;
                }

                // ---- O += P V ; l += P * ones ----
                #pragma unroll
                for (int ks = 0; ks < 8; ++ks) {
                    uint32_t pa[4] = {pha[2*ks], phb[2*ks], pha[2*ks+1], phb[2*ks+1]};
                    mma_f16(lacc, pa, ones_b);
                    #pragma unroll
                    for (int ntp = 0; ntp < 4; ++ntp) {
                        uint32_t vf[4];
                        ldsm4(vf, ss + AV + (uint32_t)(ntp*16*136 + ks*16)*2 + bvoff);
                        mma_f16(o[2*ntp],   pa, &vf[0]);
                        mma_f16(o[2*ntp+1], pa, &vf[2]);
                    }
                }

                stg ^= 1;
            }
        }

        // ---- write unnormalized partials ----
        const int rl0 = warp*16 + rql;
        float* po = &g_po[half][bq][0][0];
        #pragma unroll
        for (int nt = 0; nt < 8; ++nt) {
            const int col = nt*8 + qc;
            *(float2*)&po[(size_t)rl0*64 + col]      = make_float2(o[nt][0], o[nt][1]);
            *(float2*)&po[(size_t)(rl0+8)*64 + col]  = make_float2(o[nt][2], o[nt][3]);
        }
        if ((lane & 3) == 0) {
            g_pml[half][bq][rl0]     = make_float2(m0r, lacc[0]);
            g_pml[half][bq][rl0 + 8] = make_float2(m1r, lacc[2]);
        }

        // ---- last finisher merges (base-2 weights) ----
        __threadfence();
        __syncthreads();
        if (tid == 0) s_done = atomicAdd(&g_flag[bq], 1);
        __syncthreads();
        if (s_done == 1) {
            __threadfence();
            const int r  = tid >> 1;
            const int ch = (tid & 1) * 32;
            float2 A  = g_pml[0][bq][r];
            float2 Bv = g_pml[1][bq][r];
            float m  = fmaxf(A.x, Bv.x);
            float wA = ex2(A.x - m);
            float wB = ex2(Bv.x - m);
            float inv = 1.0f / (wA*A.y + wB*Bv.y);
            const float4* pa = (const float4*)&g_po[0][bq][r][ch];
            const float4* pb = (const float4*)&g_po[1][bq][r][ch];
            float4* pw = (float4*)&out[((size_t)(b*Tq + q0 + r))*64 + ch];
            #pragma unroll
            for (int j = 0; j < 8; ++j) {
                float4 a = pa[j], c = pb[j];
                pw[j] = make_float4((wA*a.x + wB*c.x)*inv, (wA*a.y + wB*c.y)*inv,
                                    (wA*a.z + wB*c.z)*inv, (wA*a.w + wB*c.w)*inv);
            }
        }
    }
}

// ---------------------------------------------------------------------------
extern "C" void kernel_launch(void* const* d_in, const int* in_sizes, int n_in,
                              void* d_out, int out_size)
{
    const float* x  = (const float*)d_in[0];
    const float* Wq = (const float*)d_in[1];
    const float* Wk = (const float*)d_in[2];
    const float* Wv = (const float*)d_in[3];
    float* out = (float*)d_out;

    (void)in_sizes; (void)n_in; (void)out_size;

    wsplit_kernel<<<dim3(32, 3), 256>>>(Wq, Wk, Wv);

    cudaFuncSetAttribute(qkv_gemm_kernel,
                         cudaFuncAttributeMaxDynamicSharedMemorySize, QSM_TOTAL);
    qkv_gemm_kernel<<<128, 256, QSM_TOTAL>>>(x);

    cudaFuncSetAttribute(attn_kernel,
                         cudaFuncAttributeMaxDynamicSharedMemorySize, ASM_TOTAL);
    attn_kernel<<<148, 256, ASM_TOTAL>>>(out);
}